// round 7
// baseline (speedup 1.0000x reference)
#include <cuda_runtime.h>

// FastQuantumLLMOptimized: per-position cross-head attention.
// x: [16384, 32, 128] f32, patterns: [32,128] f32.
//   xh = x_pos * patterns ; s = xh xh^T / sqrt(128); a = softmax(s); out = a xh
//
// ONE WARP = ONE CTA = ONE POSITION. fp32 with packed fma.rn.f32x2.
// Full k per thread in phase 2; softmax distributed with 2 shfl rounds;
// phase 4 is a single pass with a 4h x 32d register tile.
//
// Swizzle: xh float4 granules at h*32 + (c ^ ((h>>2)&7)); all LDS phase
// groups conflict-free (distinct row-blocks -> distinct bank groups; equal
// rows -> broadcast). attn stored transposed [g][h], stride 36.

#define NHEADS 32
#define HD 128
#define AT_ROW 36

__device__ __forceinline__ unsigned long long pack2(float lo, float hi) {
    unsigned long long r;
    asm("mov.b64 %0, {%1, %2};" : "=l"(r) : "f"(lo), "f"(hi));
    return r;
}
__device__ __forceinline__ float2 unpack2(unsigned long long v) {
    float2 r;
    asm("mov.b64 {%0, %1}, %2;" : "=f"(r.x), "=f"(r.y) : "l"(v));
    return r;
}
__device__ __forceinline__ void fma2(unsigned long long &acc,
                                     unsigned long long a,
                                     unsigned long long b) {
    asm("fma.rn.f32x2 %0, %1, %2, %0;" : "+l"(acc) : "l"(a), "l"(b));
}

__global__ __launch_bounds__(32, 11)
void fq_attn_kernel(const float* __restrict__ x,
                    const float* __restrict__ patterns,
                    float* __restrict__ out)
{
    __shared__ __align__(16) float4 s_xh4[NHEADS * 32];          // 16 KB
    __shared__ __align__(16) float  s_at [NHEADS * AT_ROW + 4];  // ~4.6 KB

    const int lane = threadIdx.x;
    const long long pos = blockIdx.x;

    float4* xh = s_xh4;
    float*  at = s_at;

    // ---------------- Phase 1: load + modulate -> swizzled smem ------------
    {
        const float4* x4 = reinterpret_cast<const float4*>(x + pos * (NHEADS * HD));
        const float4* p4 = reinterpret_cast<const float4*>(patterns);
        #pragma unroll 8
        for (int h = 0; h < 32; h++) {
            float4 xv = x4[h * 32 + lane];
            float4 pv = __ldg(&p4[h * 32 + lane]);
            float4 r;
            r.x = xv.x * pv.x; r.y = xv.y * pv.y;
            r.z = xv.z * pv.z; r.w = xv.w * pv.w;
            xh[h * 32 + (lane ^ ((h >> 2) & 7))] = r;
        }
    }
    __syncwarp();

    // ---------------- Phase 2: scores (32x32, k=128), full k per thread ----
    // lane = ht(8) x gt(4): thread computes 4h x 8g tile, all 128 k.
    {
        const int ht = lane & 7;
        const int gt = lane >> 3;
        const int h0 = ht * 4;
        const int g0 = gt * 8;

        unsigned long long acc[4][8];
        #pragma unroll
        for (int i = 0; i < 4; i++)
            #pragma unroll
            for (int j = 0; j < 8; j++) acc[i][j] = 0ULL;

        #pragma unroll 4
        for (int c = 0; c < 32; c++) {
            ulonglong2 a[4];
            #pragma unroll
            for (int i = 0; i < 4; i++)   // swizzle of row 4ht+i is ht (i<4)
                a[i] = *reinterpret_cast<const ulonglong2*>(&xh[(h0 + i) * 32 + (c ^ ht)]);
            #pragma unroll
            for (int j = 0; j < 8; j++) {
                const int sb = 2 * gt + (j >> 2);   // swizzle of row 8gt+j
                ulonglong2 b = *reinterpret_cast<const ulonglong2*>(&xh[(g0 + j) * 32 + (c ^ sb)]);
                #pragma unroll
                for (int i = 0; i < 4; i++) {
                    fma2(acc[i][j], a[i].x, b.x);
                    fma2(acc[i][j], a[i].y, b.y);
                }
            }
        }

        // collapse + softmax (rows h0..h0+3 live on the 4 lanes sharing ht;
        // g distributed: 8 in-thread + gt via shfl on lane bits 3,4 -> 8,16)
        float v[4][8];
        #pragma unroll
        for (int i = 0; i < 4; i++)
            #pragma unroll
            for (int j = 0; j < 8; j++) {
                float2 u = unpack2(acc[i][j]);
                v[i][j] = (u.x + u.y) * 0.08838834764831845f;  // 1/sqrt(128)
            }

        float inv[4];
        #pragma unroll
        for (int i = 0; i < 4; i++) {
            float m = v[i][0];
            #pragma unroll
            for (int j = 1; j < 8; j++) m = fmaxf(m, v[i][j]);
            m = fmaxf(m, __shfl_xor_sync(0xffffffffu, m, 8));
            m = fmaxf(m, __shfl_xor_sync(0xffffffffu, m, 16));
            float s = 0.0f;
            #pragma unroll
            for (int j = 0; j < 8; j++) { v[i][j] = __expf(v[i][j] - m); s += v[i][j]; }
            s += __shfl_xor_sync(0xffffffffu, s, 8);
            s += __shfl_xor_sync(0xffffffffu, s, 16);
            inv[i] = 1.0f / s;
        }

        // store attn transposed: at[g*36 + h]; per j one float4 over i rows
        #pragma unroll
        for (int j = 0; j < 8; j++) {
            float4 q = make_float4(v[0][j] * inv[0], v[1][j] * inv[1],
                                   v[2][j] * inv[2], v[3][j] * inv[3]);
            *reinterpret_cast<float4*>(&at[(g0 + j) * AT_ROW + h0]) = q;
        }
    }
    __syncwarp();

    // ---------------- Phase 3: out = attn @ xh (32x128, k=32), single pass -
    // lane = hq(8) x dt(4); thread tile 4h x 32d (granules ch = 4t+dt).
    {
        const int dt = lane & 3;
        const int hq = lane >> 2;
        const int H0 = hq * 4;
        float* outp = out + pos * (NHEADS * HD);

        unsigned long long acc[4][8][2];
        #pragma unroll
        for (int i = 0; i < 4; i++)
            #pragma unroll
            for (int t = 0; t < 8; t++) { acc[i][t][0] = 0ULL; acc[i][t][1] = 0ULL; }

        #pragma unroll 4
        for (int g = 0; g < 32; g++) {
            float4 av = *reinterpret_cast<const float4*>(&at[g * AT_ROW + H0]);
            unsigned long long a2[4];
            a2[0] = pack2(av.x, av.x);
            a2[1] = pack2(av.y, av.y);
            a2[2] = pack2(av.z, av.z);
            a2[3] = pack2(av.w, av.w);
            const int sg = (g >> 2) & 7;
            #pragma unroll
            for (int t = 0; t < 8; t++) {
                const int ch = t * 4 + dt;
                ulonglong2 bb = *reinterpret_cast<const ulonglong2*>(&xh[g * 32 + (ch ^ sg)]);
                #pragma unroll
                for (int i = 0; i < 4; i++) {
                    fma2(acc[i][t][0], a2[i], bb.x);
                    fma2(acc[i][t][1], a2[i], bb.y);
                }
            }
        }

        #pragma unroll
        for (int i = 0; i < 4; i++)
            #pragma unroll
            for (int t = 0; t < 8; t++) {
                const int ch = t * 4 + dt;
                float2 u0 = unpack2(acc[i][t][0]);
                float2 u1 = unpack2(acc[i][t][1]);
                *reinterpret_cast<float4*>(&outp[(H0 + i) * HD + ch * 4])
                    = make_float4(u0.x, u0.y, u1.x, u1.y);
            }
    }
}

extern "C" void kernel_launch(void* const* d_in, const int* in_sizes, int n_in,
                              void* d_out, int out_size) {
    const float* x        = (const float*)d_in[0];
    const float* patterns = (const float*)d_in[1];
    float* out            = (float*)d_out;
    const int positions   = in_sizes[0] / (NHEADS * HD);   // 16384
    fq_attn_kernel<<<positions, 32>>>(x, patterns, out);
}

// round 8
// speedup vs baseline: 1.0268x; 1.0268x over previous
#include <cuda_runtime.h>

// FastQuantumLLMOptimized: per-position cross-head attention.
// x: [16384, 32, 128] f32, patterns: [32,128] f32.
//   xh = x_pos * patterns ; s = xh xh^T / sqrt(128); a = softmax(s); out = a xh
//
// ONE WARP per position (CTA = 2 warps = 2 positions, 41KB static smem).
// Full k per thread in phase 2 (no partials, no __syncthreads — warps fully
// independent). fp32 with packed fma.rn.f32x2. Phase 4 is a single fused
// pass with a 4h x 32d register tile.
//
// Swizzle: xh stored as float4 granules at h*32 + (c ^ ((h>>2)&7)); every
// LDS phase group is conflict-free (distinct row-blocks -> distinct bank
// groups; equal rows -> broadcast). attn transposed [g][h], stride 36.

#define NHEADS 32
#define HD 128
#define AT_ROW 36

__device__ __forceinline__ unsigned long long pack2(float lo, float hi) {
    unsigned long long r;
    asm("mov.b64 %0, {%1, %2};" : "=l"(r) : "f"(lo), "f"(hi));
    return r;
}
__device__ __forceinline__ float2 unpack2(unsigned long long v) {
    float2 r;
    asm("mov.b64 {%0, %1}, %2;" : "=f"(r.x), "=f"(r.y) : "l"(v));
    return r;
}
__device__ __forceinline__ void fma2(unsigned long long &acc,
                                     unsigned long long a,
                                     unsigned long long b) {
    asm("fma.rn.f32x2 %0, %1, %2, %0;" : "+l"(acc) : "l"(a), "l"(b));
}

__global__ __launch_bounds__(64)
void fq_attn_kernel(const float* __restrict__ x,
                    const float* __restrict__ patterns,
                    float* __restrict__ out)
{
    __shared__ __align__(16) float4 s_xh4[2][NHEADS * 32];          // 2 x 16 KB
    __shared__ __align__(16) float  s_at [2][NHEADS * AT_ROW + 4];  // 2 x ~4.6 KB

    const int lane = threadIdx.x & 31;
    const int w    = threadIdx.x >> 5;
    const long long pos = 2LL * blockIdx.x + w;

    float4* xh = s_xh4[w];
    float*  at = s_at[w];

    // ---------------- Phase 1: load + modulate -> swizzled smem ------------
    {
        const float4* x4 = reinterpret_cast<const float4*>(x + pos * (NHEADS * HD));
        const float4* p4 = reinterpret_cast<const float4*>(patterns);
        #pragma unroll 8
        for (int h = 0; h < 32; h++) {
            float4 xv = x4[h * 32 + lane];
            float4 pv = __ldg(&p4[h * 32 + lane]);
            float4 r;
            r.x = xv.x * pv.x; r.y = xv.y * pv.y;
            r.z = xv.z * pv.z; r.w = xv.w * pv.w;
            xh[h * 32 + (lane ^ ((h >> 2) & 7))] = r;
        }
    }
    __syncwarp();

    // ---------------- Phase 2: scores (32x32, k=128), full k per thread ----
    // lane = ht(8) x gt(4): thread computes 4h x 8g tile, all 128 k.
    {
        const int ht = lane & 7;
        const int gt = lane >> 3;
        const int h0 = ht * 4;
        const int g0 = gt * 8;

        unsigned long long acc[4][8];
        #pragma unroll
        for (int i = 0; i < 4; i++)
            #pragma unroll
            for (int j = 0; j < 8; j++) acc[i][j] = 0ULL;

        #pragma unroll 4
        for (int c = 0; c < 32; c++) {
            ulonglong2 a[4];
            #pragma unroll
            for (int i = 0; i < 4; i++)   // swizzle of row 4ht+i is ht (i<4)
                a[i] = *reinterpret_cast<const ulonglong2*>(&xh[(h0 + i) * 32 + (c ^ ht)]);
            #pragma unroll
            for (int j = 0; j < 8; j++) {
                const int sb = 2 * gt + (j >> 2);   // swizzle of row 8gt+j
                ulonglong2 b = *reinterpret_cast<const ulonglong2*>(&xh[(g0 + j) * 32 + (c ^ sb)]);
                #pragma unroll
                for (int i = 0; i < 4; i++) {
                    fma2(acc[i][j], a[i].x, b.x);
                    fma2(acc[i][j], a[i].y, b.y);
                }
            }
        }

        // collapse + softmax (rows h0..h0+3 live on the 4 lanes sharing ht;
        // g distributed: 8 in-thread + gt via shfl on lane bits 3,4 -> 8,16)
        float v[4][8];
        #pragma unroll
        for (int i = 0; i < 4; i++)
            #pragma unroll
            for (int j = 0; j < 8; j++) {
                float2 u = unpack2(acc[i][j]);
                v[i][j] = (u.x + u.y) * 0.08838834764831845f;  // 1/sqrt(128)
            }

        float inv[4];
        #pragma unroll
        for (int i = 0; i < 4; i++) {
            float m = v[i][0];
            #pragma unroll
            for (int j = 1; j < 8; j++) m = fmaxf(m, v[i][j]);
            m = fmaxf(m, __shfl_xor_sync(0xffffffffu, m, 8));
            m = fmaxf(m, __shfl_xor_sync(0xffffffffu, m, 16));
            float s = 0.0f;
            #pragma unroll
            for (int j = 0; j < 8; j++) { v[i][j] = __expf(v[i][j] - m); s += v[i][j]; }
            s += __shfl_xor_sync(0xffffffffu, s, 8);
            s += __shfl_xor_sync(0xffffffffu, s, 16);
            inv[i] = 1.0f / s;
        }

        // store attn transposed: at[g*36 + h]; per j one float4 over i rows
        #pragma unroll
        for (int j = 0; j < 8; j++) {
            float4 q = make_float4(v[0][j] * inv[0], v[1][j] * inv[1],
                                   v[2][j] * inv[2], v[3][j] * inv[3]);
            *reinterpret_cast<float4*>(&at[(g0 + j) * AT_ROW + h0]) = q;
        }
    }
    __syncwarp();

    // ---------------- Phase 3: out = attn @ xh (32x128, k=32), single pass -
    // lane = hq(8) x dt(4); thread tile 4h x 32d (granules ch = 4t+dt).
    {
        const int dt = lane & 3;
        const int hq = lane >> 2;
        const int H0 = hq * 4;
        float* outp = out + pos * (NHEADS * HD);

        unsigned long long acc[4][8][2];
        #pragma unroll
        for (int i = 0; i < 4; i++)
            #pragma unroll
            for (int t = 0; t < 8; t++) { acc[i][t][0] = 0ULL; acc[i][t][1] = 0ULL; }

        #pragma unroll 4
        for (int g = 0; g < 32; g++) {
            float4 av = *reinterpret_cast<const float4*>(&at[g * AT_ROW + H0]);
            unsigned long long a2[4];
            a2[0] = pack2(av.x, av.x);
            a2[1] = pack2(av.y, av.y);
            a2[2] = pack2(av.z, av.z);
            a2[3] = pack2(av.w, av.w);
            const int sg = (g >> 2) & 7;
            #pragma unroll
            for (int t = 0; t < 8; t++) {
                const int ch = t * 4 + dt;
                ulonglong2 bb = *reinterpret_cast<const ulonglong2*>(&xh[g * 32 + (ch ^ sg)]);
                #pragma unroll
                for (int i = 0; i < 4; i++) {
                    fma2(acc[i][t][0], a2[i], bb.x);
                    fma2(acc[i][t][1], a2[i], bb.y);
                }
            }
        }

        #pragma unroll
        for (int i = 0; i < 4; i++)
            #pragma unroll
            for (int t = 0; t < 8; t++) {
                const int ch = t * 4 + dt;
                float2 u0 = unpack2(acc[i][t][0]);
                float2 u1 = unpack2(acc[i][t][1]);
                *reinterpret_cast<float4*>(&outp[(H0 + i) * HD + ch * 4])
                    = make_float4(u0.x, u0.y, u1.x, u1.y);
            }
    }
}

extern "C" void kernel_launch(void* const* d_in, const int* in_sizes, int n_in,
                              void* d_out, int out_size) {
    const float* x        = (const float*)d_in[0];
    const float* patterns = (const float*)d_in[1];
    float* out            = (float*)d_out;
    const int positions   = in_sizes[0] / (NHEADS * HD);   // 16384 (even)
    fq_attn_kernel<<<positions / 2, 64>>>(x, patterns, out);
}

// round 9
// speedup vs baseline: 1.1096x; 1.0806x over previous
#include <cuda_runtime.h>
#include <cuda_fp16.h>

// FastQuantumLLMOptimized: per-position cross-head attention.
// x: [16384, 32, 128] f32, patterns: [32,128] f32.
//   xh = x_pos * patterns ; s = xh xh^T / sqrt(128); a = softmax(s); out = a xh
//
// ONE WARP per position (CTA = 2 warps = 2 positions). fp32 math with packed
// fma.rn.f32x2; attention weights stored fp16 in smem (range [0,1], eps 5e-4
// << 1e-3 gate) to shrink smem to ~37KB/CTA -> 6 CTAs/SM (12 warps, +20% occ
// vs fp32 attn).  Structure otherwise identical to the validated 206us kernel.
//
// Swizzle: xh float4 granules at h*32 + (c ^ ((h>>2)&7)); every LDS phase
// group conflict-free (distinct row-blocks -> distinct bank groups; equal
// rows -> broadcast). attn transposed [g][h], 32 halves per row (64B).

#define NHEADS 32
#define HD 128

__device__ __forceinline__ unsigned long long pack2(float lo, float hi) {
    unsigned long long r;
    asm("mov.b64 %0, {%1, %2};" : "=l"(r) : "f"(lo), "f"(hi));
    return r;
}
__device__ __forceinline__ float2 unpack2(unsigned long long v) {
    float2 r;
    asm("mov.b64 {%0, %1}, %2;" : "=f"(r.x), "=f"(r.y) : "l"(v));
    return r;
}
__device__ __forceinline__ void fma2(unsigned long long &acc,
                                     unsigned long long a,
                                     unsigned long long b) {
    asm("fma.rn.f32x2 %0, %1, %2, %0;" : "+l"(acc) : "l"(a), "l"(b));
}

__global__ __launch_bounds__(64)
void fq_attn_kernel(const float* __restrict__ x,
                    const float* __restrict__ patterns,
                    float* __restrict__ out)
{
    __shared__ __align__(16) float4 s_xh4[2][NHEADS * 32];        // 2 x 16 KB
    __shared__ __align__(16) __half s_at [2][NHEADS * 32 + 16];   // 2 x ~2 KB

    const int lane = threadIdx.x & 31;
    const int w    = threadIdx.x >> 5;
    const long long pos = 2LL * blockIdx.x + w;

    float4* xh = s_xh4[w];
    __half* at = s_at[w];

    // ---------------- Phase 1: load + modulate -> swizzled smem ------------
    {
        const float4* x4 = reinterpret_cast<const float4*>(x + pos * (NHEADS * HD));
        const float4* p4 = reinterpret_cast<const float4*>(patterns);
        #pragma unroll 8
        for (int h = 0; h < 32; h++) {
            float4 xv = x4[h * 32 + lane];
            float4 pv = __ldg(&p4[h * 32 + lane]);
            float4 r;
            r.x = xv.x * pv.x; r.y = xv.y * pv.y;
            r.z = xv.z * pv.z; r.w = xv.w * pv.w;
            xh[h * 32 + (lane ^ ((h >> 2) & 7))] = r;
        }
    }
    __syncwarp();

    // ---------------- Phase 2: scores (32x32, k=128), full k per thread ----
    // lane = ht(8) x gt(4): thread computes 4h x 8g tile, all 128 k.
    {
        const int ht = lane & 7;
        const int gt = lane >> 3;
        const int h0 = ht * 4;
        const int g0 = gt * 8;

        unsigned long long acc[4][8];
        #pragma unroll
        for (int i = 0; i < 4; i++)
            #pragma unroll
            for (int j = 0; j < 8; j++) acc[i][j] = 0ULL;

        #pragma unroll 4
        for (int c = 0; c < 32; c++) {
            ulonglong2 a[4];
            #pragma unroll
            for (int i = 0; i < 4; i++)   // swizzle of row 4ht+i is ht (i<4)
                a[i] = *reinterpret_cast<const ulonglong2*>(&xh[(h0 + i) * 32 + (c ^ ht)]);
            #pragma unroll
            for (int j = 0; j < 8; j++) {
                const int sb = 2 * gt + (j >> 2);   // swizzle of row 8gt+j
                ulonglong2 b = *reinterpret_cast<const ulonglong2*>(&xh[(g0 + j) * 32 + (c ^ sb)]);
                #pragma unroll
                for (int i = 0; i < 4; i++) {
                    fma2(acc[i][j], a[i].x, b.x);
                    fma2(acc[i][j], a[i].y, b.y);
                }
            }
        }

        // collapse + softmax (rows h0..h0+3 on the 4 lanes sharing ht;
        // g distributed: 8 in-thread + gt via shfl on lane bits 3,4 -> 8,16)
        float v[4][8];
        #pragma unroll
        for (int i = 0; i < 4; i++)
            #pragma unroll
            for (int j = 0; j < 8; j++) {
                float2 u = unpack2(acc[i][j]);
                v[i][j] = (u.x + u.y) * 0.08838834764831845f;  // 1/sqrt(128)
            }

        float inv[4];
        #pragma unroll
        for (int i = 0; i < 4; i++) {
            float m = v[i][0];
            #pragma unroll
            for (int j = 1; j < 8; j++) m = fmaxf(m, v[i][j]);
            m = fmaxf(m, __shfl_xor_sync(0xffffffffu, m, 8));
            m = fmaxf(m, __shfl_xor_sync(0xffffffffu, m, 16));
            float s = 0.0f;
            #pragma unroll
            for (int j = 0; j < 8; j++) { v[i][j] = __expf(v[i][j] - m); s += v[i][j]; }
            s += __shfl_xor_sync(0xffffffffu, s, 8);
            s += __shfl_xor_sync(0xffffffffu, s, 16);
            inv[i] = 1.0f / s;
        }

        // store attn transposed fp16: at[g*32 + h]; per j one 8B store (4 h)
        #pragma unroll
        for (int j = 0; j < 8; j++) {
            __half2 q0 = __floats2half2_rn(v[0][j] * inv[0], v[1][j] * inv[1]);
            __half2 q1 = __floats2half2_rn(v[2][j] * inv[2], v[3][j] * inv[3]);
            uint2 q;
            q.x = *reinterpret_cast<unsigned int*>(&q0);
            q.y = *reinterpret_cast<unsigned int*>(&q1);
            *reinterpret_cast<uint2*>(&at[(g0 + j) * 32 + h0]) = q;
        }
    }
    __syncwarp();

    // ---------------- Phase 3: out = attn @ xh (32x128, k=32) --------------
    // lane = hq(8) x dt(4); two d-half passes; thread tile 4h x 16d per pass.
    {
        const int dt = lane & 3;
        const int hq = lane >> 2;
        const int H0 = hq * 4;
        float* outp = out + pos * (NHEADS * HD);

        for (int p = 0; p < 2; p++) {
            unsigned long long acc[4][4][2];
            #pragma unroll
            for (int i = 0; i < 4; i++)
                #pragma unroll
                for (int t = 0; t < 4; t++) { acc[i][t][0] = 0ULL; acc[i][t][1] = 0ULL; }

            #pragma unroll 4
            for (int g = 0; g < 32; g++) {
                uint2 qa = *reinterpret_cast<const uint2*>(&at[g * 32 + H0]);
                float2 f01 = __half22float2(*reinterpret_cast<__half2*>(&qa.x));
                float2 f23 = __half22float2(*reinterpret_cast<__half2*>(&qa.y));
                unsigned long long a2[4];
                a2[0] = pack2(f01.x, f01.x);
                a2[1] = pack2(f01.y, f01.y);
                a2[2] = pack2(f23.x, f23.x);
                a2[3] = pack2(f23.y, f23.y);
                const int sg = (g >> 2) & 7;
                #pragma unroll
                for (int t = 0; t < 4; t++) {
                    const int ch = p * 16 + t * 4 + dt;
                    ulonglong2 bb = *reinterpret_cast<const ulonglong2*>(&xh[g * 32 + (ch ^ sg)]);
                    #pragma unroll
                    for (int i = 0; i < 4; i++) {
                        fma2(acc[i][t][0], a2[i], bb.x);
                        fma2(acc[i][t][1], a2[i], bb.y);
                    }
                }
            }

            #pragma unroll
            for (int i = 0; i < 4; i++)
                #pragma unroll
                for (int t = 0; t < 4; t++) {
                    const int ch = p * 16 + t * 4 + dt;
                    float2 u0 = unpack2(acc[i][t][0]);
                    float2 u1 = unpack2(acc[i][t][1]);
                    *reinterpret_cast<float4*>(&outp[(H0 + i) * HD + ch * 4])
                        = make_float4(u0.x, u0.y, u1.x, u1.y);
                }
        }
    }
}

extern "C" void kernel_launch(void* const* d_in, const int* in_sizes, int n_in,
                              void* d_out, int out_size) {
    const float* x        = (const float*)d_in[0];
    const float* patterns = (const float*)d_in[1];
    float* out            = (float*)d_out;
    const int positions   = in_sizes[0] / (NHEADS * HD);   // 16384 (even)
    fq_attn_kernel<<<positions / 2, 64>>>(x, patterns, out);
}